// round 1
// baseline (speedup 1.0000x reference)
#include <cuda_runtime.h>
#include <math.h>

#define N_NODES 512
#define BATCH   128
#define UNITS   64
#define M_DIFF  5
#define E_EDGES 8192
#define T_INS   12
#define T_OUTS  12
#define NB      (N_NODES*BATCH)   // 65536
#define C0      65                // 1 + UNITS
#define C1      128               // UNITS + UNITS
#define K0      (C0*M_DIFF)       // 325
#define K1      (C1*M_DIFF)       // 640
#define LDA0    328               // K0 padded to mult of 4 for float4
#define LDA1    640

// ---------------- scratch (static __device__, no allocation) ----------------
__device__ float g_A[N_NODES*N_NODES];
__device__ float g_invrow[N_NODES];
__device__ float g_invcol[N_NODES];
__device__ int   g_cnt1[N_NODES], g_cnt2[N_NODES];
__device__ int   g_ptr1[N_NODES+1], g_ptr2[N_NODES+1];
__device__ int   g_cur1[N_NODES], g_cur2[N_NODES];
__device__ int   g_col1[E_EDGES], g_col2[E_EDGES];
__device__ float g_val1[E_EDGES], g_val2[E_EDGES];
__device__ float g_XS[NB*LDA1];            // [N,B,M*C] diffusion stack (max layer1)
__device__ float g_Gg[NB*2*UNITS];         // gates (post-sigmoid) [N,B,128]
__device__ float g_Gc[NB*UNITS];           // candidate (post-tanh) [N,B,64]
__device__ float g_h0[NB*UNITS];           // hidden layer0 [N,B,64]
__device__ float g_h1[NB*UNITS];           // hidden layer1 [N,B,64]
__device__ float g_xin[NB];                // current input, [n*B+b]
__device__ float g_Wg0[K0*2*UNITS];        // permuted weights (k = m*C+c)
__device__ float g_Wc0[K0*UNITS];
__device__ float g_Wg1[K1*2*UNITS];
__device__ float g_Wc1[K1*UNITS];

// ---------------- setup kernels ----------------
__global__ void zero_setup_k() {
    int idx = blockIdx.x * 256 + threadIdx.x;
    if (idx < N_NODES*N_NODES) g_A[idx] = 0.f;
    if (idx < N_NODES) { g_cnt1[idx]=0; g_cnt2[idx]=0; g_cur1[idx]=0; g_cur2[idx]=0; }
}
__global__ void zero_h_k() {
    int idx = blockIdx.x * 256 + threadIdx.x;
    if (idx < NB*UNITS) { g_h0[idx] = 0.f; g_h1[idx] = 0.f; }
}
__global__ void zero_xin_k() {
    int idx = blockIdx.x * 256 + threadIdx.x;
    if (idx < NB) g_xin[idx] = 0.f;
}
__global__ void scatter_k(const int* __restrict__ ei, const float* __restrict__ ea) {
    int e = blockIdx.x * 256 + threadIdx.x;
    if (e < E_EDGES) atomicAdd(&g_A[ei[e]*N_NODES + ei[E_EDGES+e]], ea[e]);
}
__global__ void rowinv_k() {
    __shared__ float sh[256];
    int r = blockIdx.x;
    float s = 0.f;
    for (int j = threadIdx.x; j < N_NODES; j += 256) s += g_A[r*N_NODES + j];
    sh[threadIdx.x] = s; __syncthreads();
    for (int o = 128; o > 0; o >>= 1) {
        if (threadIdx.x < o) sh[threadIdx.x] += sh[threadIdx.x + o];
        __syncthreads();
    }
    if (threadIdx.x == 0) { float d = sh[0]; g_invrow[r] = d > 0.f ? 1.f/d : 0.f; }
}
__global__ void colinv_k() {
    int c = blockIdx.x * 256 + threadIdx.x;
    if (c < N_NODES) {
        float s = 0.f;
        for (int i = 0; i < N_NODES; i++) s += g_A[i*N_NODES + c];
        g_invcol[c] = s > 0.f ? 1.f/s : 0.f;
    }
}
__global__ void count_k() {
    int idx = blockIdx.x * 256 + threadIdx.x;
    if (idx >= N_NODES*N_NODES) return;
    if (g_A[idx] != 0.f) {
        int i = idx / N_NODES, j = idx - i*N_NODES;
        atomicAdd(&g_cnt2[i], 1);   // S2 rows = rows of A
        atomicAdd(&g_cnt1[j], 1);   // S1 rows = cols of A
    }
}
__global__ void scan_k() {
    if (threadIdx.x == 0) {
        int s = 0;
        for (int i = 0; i < N_NODES; i++) { g_ptr1[i] = s; s += g_cnt1[i]; }
        g_ptr1[N_NODES] = s;
    }
    if (threadIdx.x == 1) {
        int s = 0;
        for (int i = 0; i < N_NODES; i++) { g_ptr2[i] = s; s += g_cnt2[i]; }
        g_ptr2[N_NODES] = s;
    }
}
__global__ void fill_k() {
    int idx = blockIdx.x * 256 + threadIdx.x;
    if (idx >= N_NODES*N_NODES) return;
    float a = g_A[idx];
    if (a != 0.f) {
        int i = idx / N_NODES, j = idx - i*N_NODES;
        // S2[i][j] = A[i][j] * invcol[j]
        int p2 = atomicAdd(&g_cur2[i], 1);
        int o2 = g_ptr2[i] + p2;
        g_col2[o2] = j; g_val2[o2] = a * g_invcol[j];
        // S1[j][i] = A[i][j] * invrow[i]
        int p1 = atomicAdd(&g_cur1[j], 1);
        int o1 = g_ptr1[j] + p1;
        g_col1[o1] = i; g_val1[o1] = a * g_invrow[i];
    }
}
// permute W[(c*M+m)*OUT+o] -> Wp[(m*C+c)*OUT+o]
__global__ void permW_k(const float* __restrict__ W, int dsel, int C, int OUT) {
    int idx = blockIdx.x * 256 + threadIdx.x;
    int tot = C * M_DIFF * OUT;
    if (idx >= tot) return;
    int o = idx % OUT, r = idx / OUT;
    int m = r / C, c = r - m*C;
    float* dst = (dsel==0) ? g_Wg0 : (dsel==1) ? g_Wc0 : (dsel==2) ? g_Wg1 : g_Wc1;
    dst[idx] = W[(c*M_DIFF + m)*OUT + o];
}

// ---------------- per-step kernels ----------------
__global__ void transpose_in_k(const float* __restrict__ hist_t) {
    int idx = blockIdx.x * 256 + threadIdx.x;   // idx = b*512 + n
    if (idx >= NB) return;
    int b = idx >> 9, n = idx & 511;
    g_xin[n*BATCH + b] = hist_t[idx];
}
__global__ void concat_g0_k() {
    int idx = blockIdx.x * 256 + threadIdx.x;
    if (idx >= NB*C0) return;
    int nb = idx / C0, c = idx - nb*C0;
    g_XS[nb*LDA0 + c] = (c == 0) ? g_xin[nb] : g_h0[nb*UNITS + c - 1];
}
__global__ void concat_c0_k() {
    int idx = blockIdx.x * 256 + threadIdx.x;
    if (idx >= NB*C0) return;
    int nb = idx / C0, c = idx - nb*C0;
    g_XS[nb*LDA0 + c] = (c == 0) ? g_xin[nb]
                                 : g_Gg[nb*(2*UNITS) + c - 1] * g_h0[nb*UNITS + c - 1];
}
__global__ void concat_g1_k() {
    int idx = blockIdx.x * 256 + threadIdx.x;
    if (idx >= NB*C1) return;
    int nb = idx >> 7, c = idx & 127;
    g_XS[nb*LDA1 + c] = (c < UNITS) ? g_h0[nb*UNITS + c] : g_h1[nb*UNITS + c - UNITS];
}
__global__ void concat_c1_k() {
    int idx = blockIdx.x * 256 + threadIdx.x;
    if (idx >= NB*C1) return;
    int nb = idx >> 7, c = idx & 127;
    g_XS[nb*LDA1 + c] = (c < UNITS) ? g_h0[nb*UNITS + c]
                                    : g_Gg[nb*(2*UNITS) + (c - UNITS)] * g_h1[nb*UNITS + c - UNITS];
}

// SpMM: XS[:, off_out] = S @ XS[:, off_in]  (optionally 2*S@x - x0, Chebyshev)
__global__ __launch_bounds__(256) void spmm_k(int sup, int C, int LDAv,
                                              int off_in, int off_out, int cheb) {
    const int*   rp = (sup == 1) ? g_ptr1 : g_ptr2;
    const int*   ci = (sup == 1) ? g_col1 : g_col2;
    const float* cv = (sup == 1) ? g_val1 : g_val2;
    int n  = blockIdx.x;
    int BC = BATCH * C;
    int j0 = blockIdx.y * 1024 + threadIdx.x;
    int inb[4]; float acc[4] = {0.f, 0.f, 0.f, 0.f};
#pragma unroll
    for (int i = 0; i < 4; i++) {
        int j = j0 + i*256;
        if (j < BC) { int b = j / C; int c = j - b*C; inb[i] = b*LDAv + off_in + c; }
        else inb[i] = -1;
    }
    int e0 = rp[n], e1 = rp[n+1];
    int rowstride = BATCH * LDAv;
    for (int e = e0; e < e1; e++) {
        int nbr = ci[e]; float v = cv[e];
        int base = nbr * rowstride;
#pragma unroll
        for (int i = 0; i < 4; i++)
            if (inb[i] >= 0) acc[i] += v * g_XS[base + inb[i]];
    }
    int obase = n * rowstride;
#pragma unroll
    for (int i = 0; i < 4; i++) {
        if (inb[i] >= 0) {
            float r = acc[i];
            if (cheb) r = 2.f*r - g_XS[obase + inb[i] - off_in];
            g_XS[obase + inb[i] - off_in + off_out] = r;
        }
    }
}

// GEMM: Out[65536, OUT] = act( XS[65536, K(lda)] @ Wp[K, OUT] + bias )
// BM=128 BN=64 BK=16, 256 threads, 8x4 per thread. ACT: 1=sigmoid, 2=tanh
template<int ACT>
__global__ __launch_bounds__(256) void gemm_k(int wsel, const float* __restrict__ bias,
                                              int outsel, int K, int lda, int OUT) {
    const float* __restrict__ Wp = (wsel==0) ? g_Wg0 : (wsel==1) ? g_Wc0
                                  : (wsel==2) ? g_Wg1 : g_Wc1;
    float* __restrict__ Out = outsel ? g_Gc : g_Gg;
    __shared__ float As[16][128];
    __shared__ float Bs[16][64];
    int tid = threadIdx.x;
    int m0 = blockIdx.x * 128;
    int n0 = blockIdx.y * 64;
    int tx = tid & 15, ty = tid >> 4;
    int arow = tid >> 2;            // 0..63
    int akc  = (tid & 3) << 2;      // 0,4,8,12
    int bkr  = tid >> 4;            // 0..15
    int bnc  = (tid & 15) << 2;     // 0..60
    const float* Abase = g_XS + (size_t)(m0 + arow) * lda + akc;
    float acc[8][4];
#pragma unroll
    for (int i = 0; i < 8; i++)
#pragma unroll
        for (int j = 0; j < 4; j++) acc[i][j] = 0.f;

    int nkt = (K + 15) >> 4;
    for (int kt = 0; kt < nkt; kt++) {
        int k0 = kt << 4;
        // A loads: pad region may hold stale finite data; zeroed B rows make it inert
        float4 a0 = *(const float4*)(Abase + k0);
        float4 a1 = *(const float4*)(Abase + (size_t)64 * lda + k0);
        int kg = k0 + bkr;
        float4 bv4 = make_float4(0.f, 0.f, 0.f, 0.f);
        if (kg < K) bv4 = *(const float4*)(Wp + (size_t)kg * OUT + n0 + bnc);
        As[akc+0][arow] = a0.x; As[akc+1][arow] = a0.y;
        As[akc+2][arow] = a0.z; As[akc+3][arow] = a0.w;
        As[akc+0][arow+64] = a1.x; As[akc+1][arow+64] = a1.y;
        As[akc+2][arow+64] = a1.z; As[akc+3][arow+64] = a1.w;
        *(float4*)&Bs[bkr][bnc] = bv4;
        __syncthreads();
#pragma unroll
        for (int k = 0; k < 16; k++) {
            float4 A0 = *(const float4*)&As[k][ty*8];
            float4 A1 = *(const float4*)&As[k][ty*8 + 4];
            float4 Bv = *(const float4*)&Bs[k][tx*4];
            float av[8] = {A0.x,A0.y,A0.z,A0.w,A1.x,A1.y,A1.z,A1.w};
            float bw[4] = {Bv.x,Bv.y,Bv.z,Bv.w};
#pragma unroll
            for (int i = 0; i < 8; i++)
#pragma unroll
                for (int j = 0; j < 4; j++) acc[i][j] += av[i] * bw[j];
        }
        __syncthreads();
    }
    float bb[4];
#pragma unroll
    for (int j = 0; j < 4; j++) bb[j] = bias[n0 + tx*4 + j];
#pragma unroll
    for (int i = 0; i < 8; i++) {
        int row = m0 + ty*8 + i;
        float4 r;
        float v0 = acc[i][0] + bb[0], v1 = acc[i][1] + bb[1];
        float v2 = acc[i][2] + bb[2], v3 = acc[i][3] + bb[3];
        if (ACT == 1) {
            v0 = 1.f/(1.f+expf(-v0)); v1 = 1.f/(1.f+expf(-v1));
            v2 = 1.f/(1.f+expf(-v2)); v3 = 1.f/(1.f+expf(-v3));
        } else {
            v0 = tanhf(v0); v1 = tanhf(v1); v2 = tanhf(v2); v3 = tanhf(v3);
        }
        r.x = v0; r.y = v1; r.z = v2; r.w = v3;
        *(float4*)(Out + (size_t)row * OUT + n0 + tx*4) = r;
    }
}

__global__ void update_k(int hsel) {
    int idx = blockIdx.x * 256 + threadIdx.x;
    if (idx >= NB*UNITS) return;
    int nb = idx >> 6, k = idx & 63;
    float u = g_Gg[(nb << 7) + UNITS + k];
    float* h = hsel ? g_h1 : g_h0;
    h[idx] = u * h[idx] + (1.f - u) * g_Gc[idx];
}
__global__ void proj_k(const float* __restrict__ pw, const float* __restrict__ pb,
                       float* __restrict__ out, int t) {
    int idx = blockIdx.x * 256 + threadIdx.x;
    if (idx >= NB) return;
    int n = idx >> 7, b = idx & 127;
    float s = pb[0];
    const float* hh = &g_h1[idx * UNITS];
#pragma unroll
    for (int k = 0; k < UNITS; k++) s += hh[k] * pw[k];
    out[(b * T_OUTS + t) * N_NODES + n] = s;
    g_xin[idx] = s;   // next decoder input
}

// ---------------- host orchestration ----------------
static void spmm4(int layer) {
    int C = layer ? C1 : C0;
    int L = layer ? LDA1 : LDA0;
    dim3 g(N_NODES, (BATCH*C + 1023) / 1024);
    spmm_k<<<g, 256>>>(1, C, L, 0,   C,   0);   // x1 = S1 @ x0
    spmm_k<<<g, 256>>>(1, C, L, C,   2*C, 1);   // x2 = 2*S1@x1 - x0
    spmm_k<<<g, 256>>>(2, C, L, 0,   3*C, 0);   // x3 = S2 @ x0
    spmm_k<<<g, 256>>>(2, C, L, 3*C, 4*C, 1);   // x4 = 2*S2@x3 - x0
}
static void launch_cell(int layer, const float* bg, const float* bc) {
    if (layer == 0) {
        concat_g0_k<<<(NB*C0 + 255)/256, 256>>>();
        spmm4(0);
        gemm_k<1><<<dim3(NB/128, 2), 256>>>(0, bg, 0, K0, LDA0, 2*UNITS);
        concat_c0_k<<<(NB*C0 + 255)/256, 256>>>();
        spmm4(0);
        gemm_k<2><<<dim3(NB/128, 1), 256>>>(1, bc, 1, K0, LDA0, UNITS);
        update_k<<<(NB*UNITS + 255)/256, 256>>>(0);
    } else {
        concat_g1_k<<<(NB*C1 + 255)/256, 256>>>();
        spmm4(1);
        gemm_k<1><<<dim3(NB/128, 2), 256>>>(2, bg, 0, K1, LDA1, 2*UNITS);
        concat_c1_k<<<(NB*C1 + 255)/256, 256>>>();
        spmm4(1);
        gemm_k<2><<<dim3(NB/128, 1), 256>>>(3, bc, 1, K1, LDA1, UNITS);
        update_k<<<(NB*UNITS + 255)/256, 256>>>(1);
    }
}

extern "C" void kernel_launch(void* const* d_in, const int* in_sizes, int n_in,
                              void* d_out, int out_size) {
    const float* hist = (const float*)d_in[0];
    const int*   ei   = (const int*)d_in[1];
    const float* ea   = (const float*)d_in[2];
    const float* W[16];
    for (int i = 0; i < 16; i++) W[i] = (const float*)d_in[3 + i];
    // W[0..7]: enc Wg0,bg0,Wc0,bc0,Wg1,bg1,Wc1,bc1 ; W[8..15]: dec same
    const float* pw = (const float*)d_in[19];
    const float* pb = (const float*)d_in[20];
    float* out = (float*)d_out;

    // --- supports setup ---
    zero_setup_k<<<(N_NODES*N_NODES)/256, 256>>>();
    zero_h_k<<<(NB*UNITS + 255)/256, 256>>>();
    scatter_k<<<E_EDGES/256, 256>>>(ei, ea);
    rowinv_k<<<N_NODES, 256>>>();
    colinv_k<<<2, 256>>>();
    count_k<<<(N_NODES*N_NODES)/256, 256>>>();
    scan_k<<<1, 32>>>();
    fill_k<<<(N_NODES*N_NODES)/256, 256>>>();

    // --- permute encoder weights ---
    permW_k<<<(K0*2*UNITS + 255)/256, 256>>>(W[0], 0, C0, 2*UNITS);
    permW_k<<<(K0*UNITS   + 255)/256, 256>>>(W[2], 1, C0, UNITS);
    permW_k<<<(K1*2*UNITS + 255)/256, 256>>>(W[4], 2, C1, 2*UNITS);
    permW_k<<<(K1*UNITS   + 255)/256, 256>>>(W[6], 3, C1, UNITS);

    // --- encoder ---
    for (int t = 0; t < T_INS; t++) {
        transpose_in_k<<<(NB + 255)/256, 256>>>(hist + (size_t)t * NB);
        launch_cell(0, W[1], W[3]);
        launch_cell(1, W[5], W[7]);
    }

    // --- permute decoder weights ---
    permW_k<<<(K0*2*UNITS + 255)/256, 256>>>(W[8],  0, C0, 2*UNITS);
    permW_k<<<(K0*UNITS   + 255)/256, 256>>>(W[10], 1, C0, UNITS);
    permW_k<<<(K1*2*UNITS + 255)/256, 256>>>(W[12], 2, C1, 2*UNITS);
    permW_k<<<(K1*UNITS   + 255)/256, 256>>>(W[14], 3, C1, UNITS);

    // --- decoder ---
    zero_xin_k<<<(NB + 255)/256, 256>>>();   // go symbol
    for (int t = 0; t < T_OUTS; t++) {
        launch_cell(0, W[9],  W[11]);
        launch_cell(1, W[13], W[15]);
        proj_k<<<(NB + 255)/256, 256>>>(pw, pb, out, t);
    }
}

// round 2
// speedup vs baseline: 1.1385x; 1.1385x over previous
#include <cuda_runtime.h>
#include <math.h>

#define N_NODES 512
#define BATCH   128
#define UNITS   64
#define M_DIFF  5
#define E_EDGES 8192
#define T_INS   12
#define T_OUTS  12
#define NB      (N_NODES*BATCH)   // 65536
#define C0      65                // 1 + UNITS
#define C1      128               // UNITS + UNITS
#define K0      (C0*M_DIFF)       // 325
#define K1      (C1*M_DIFF)       // 640
#define K0P     352               // K0 padded to mult of 32
#define LDA0    352
#define LDA1    640

// ---------------- scratch (static __device__, no allocation) ----------------
__device__ float g_A[N_NODES*N_NODES];
__device__ float g_invrow[N_NODES];
__device__ float g_invcol[N_NODES];
__device__ int   g_cnt1[N_NODES], g_cnt2[N_NODES];
__device__ int   g_ptr1[N_NODES+1], g_ptr2[N_NODES+1];
__device__ int   g_cur1[N_NODES], g_cur2[N_NODES];
__device__ int   g_col1[E_EDGES], g_col2[E_EDGES];
__device__ float g_val1[E_EDGES], g_val2[E_EDGES];
__device__ float g_XS0[NB*LDA0];           // layer0 diffusion stack [N,B, m*C0+c], pad cols zero
__device__ float g_XS1[NB*LDA1];           // layer1 diffusion stack [N,B, m*C1+c]
__device__ float g_Gg[NB*2*UNITS];         // gates (post-sigmoid) [N,B,128]
__device__ float g_Gc[NB*UNITS];           // candidate (post-tanh) [N,B,64]
__device__ float g_h0[NB*UNITS];           // hidden layer0 [N,B,64]
__device__ float g_h1[NB*UNITS];           // hidden layer1 [N,B,64]
__device__ float g_xin[NB];                // current input, [n*B+b]
__device__ float g_Wg0[K0P*2*UNITS];       // permuted weights (k = m*C+c), pad rows zero
__device__ float g_Wc0[K0P*UNITS];
__device__ float g_Wg1[K1*2*UNITS];
__device__ float g_Wc1[K1*UNITS];

// ---------------- setup kernels ----------------
__global__ void zero_setup_k() {
    int idx = blockIdx.x * 256 + threadIdx.x;
    if (idx < N_NODES*N_NODES) g_A[idx] = 0.f;
    if (idx < N_NODES) { g_cnt1[idx]=0; g_cnt2[idx]=0; g_cur1[idx]=0; g_cur2[idx]=0; }
}
__global__ void zero_h_k() {
    int idx = blockIdx.x * 256 + threadIdx.x;
    if (idx < NB*UNITS) { g_h0[idx] = 0.f; g_h1[idx] = 0.f; }
}
__global__ void zero_xin_k() {
    int idx = blockIdx.x * 256 + threadIdx.x;
    if (idx < NB) g_xin[idx] = 0.f;
}
__global__ void scatter_k(const int* __restrict__ ei, const float* __restrict__ ea) {
    int e = blockIdx.x * 256 + threadIdx.x;
    if (e < E_EDGES) atomicAdd(&g_A[ei[e]*N_NODES + ei[E_EDGES+e]], ea[e]);
}
__global__ void rowinv_k() {
    __shared__ float sh[256];
    int r = blockIdx.x;
    float s = 0.f;
    for (int j = threadIdx.x; j < N_NODES; j += 256) s += g_A[r*N_NODES + j];
    sh[threadIdx.x] = s; __syncthreads();
    for (int o = 128; o > 0; o >>= 1) {
        if (threadIdx.x < o) sh[threadIdx.x] += sh[threadIdx.x + o];
        __syncthreads();
    }
    if (threadIdx.x == 0) { float d = sh[0]; g_invrow[r] = d > 0.f ? 1.f/d : 0.f; }
}
__global__ void colinv_k() {
    int c = blockIdx.x * 256 + threadIdx.x;
    if (c < N_NODES) {
        float s = 0.f;
        for (int i = 0; i < N_NODES; i++) s += g_A[i*N_NODES + c];
        g_invcol[c] = s > 0.f ? 1.f/s : 0.f;
    }
}
__global__ void count_k() {
    int idx = blockIdx.x * 256 + threadIdx.x;
    if (idx >= N_NODES*N_NODES) return;
    if (g_A[idx] != 0.f) {
        int i = idx / N_NODES, j = idx - i*N_NODES;
        atomicAdd(&g_cnt2[i], 1);
        atomicAdd(&g_cnt1[j], 1);
    }
}
__global__ void scan_k() {
    if (threadIdx.x == 0) {
        int s = 0;
        for (int i = 0; i < N_NODES; i++) { g_ptr1[i] = s; s += g_cnt1[i]; }
        g_ptr1[N_NODES] = s;
    }
    if (threadIdx.x == 1) {
        int s = 0;
        for (int i = 0; i < N_NODES; i++) { g_ptr2[i] = s; s += g_cnt2[i]; }
        g_ptr2[N_NODES] = s;
    }
}
__global__ void fill_k() {
    int idx = blockIdx.x * 256 + threadIdx.x;
    if (idx >= N_NODES*N_NODES) return;
    float a = g_A[idx];
    if (a != 0.f) {
        int i = idx / N_NODES, j = idx - i*N_NODES;
        int p2 = atomicAdd(&g_cur2[i], 1);
        int o2 = g_ptr2[i] + p2;
        g_col2[o2] = j; g_val2[o2] = a * g_invcol[j];
        int p1 = atomicAdd(&g_cur1[j], 1);
        int o1 = g_ptr1[j] + p1;
        g_col1[o1] = i; g_val1[o1] = a * g_invrow[i];
    }
}
// permute W[(c*M+m)*OUT+o] -> Wp[(m*C+c)*OUT+o]
__global__ void permW_k(const float* __restrict__ W, int dsel, int C, int OUT) {
    int idx = blockIdx.x * 256 + threadIdx.x;
    int tot = C * M_DIFF * OUT;
    if (idx >= tot) return;
    int o = idx % OUT, r = idx / OUT;
    int m = r / C, c = r - m*C;
    float* dst = (dsel==0) ? g_Wg0 : (dsel==1) ? g_Wc0 : (dsel==2) ? g_Wg1 : g_Wc1;
    dst[idx] = W[(c*M_DIFF + m)*OUT + o];
}

// ---------------- per-step kernels ----------------
__global__ void transpose_in_k(const float* __restrict__ hist_t) {
    int idx = blockIdx.x * 256 + threadIdx.x;
    if (idx >= NB) return;
    int b = idx >> 9, n = idx & 511;
    g_xin[n*BATCH + b] = hist_t[idx];
}
__global__ void concat_g0_k() {
    int idx = blockIdx.x * 256 + threadIdx.x;
    if (idx >= NB*C0) return;
    int nb = idx / C0, c = idx - nb*C0;
    g_XS0[nb*LDA0 + c] = (c == 0) ? g_xin[nb] : g_h0[nb*UNITS + c - 1];
}
__global__ void concat_c0_k() {
    int idx = blockIdx.x * 256 + threadIdx.x;
    if (idx >= NB*C0) return;
    int nb = idx / C0, c = idx - nb*C0;
    g_XS0[nb*LDA0 + c] = (c == 0) ? g_xin[nb]
                                  : g_Gg[nb*(2*UNITS) + c - 1] * g_h0[nb*UNITS + c - 1];
}
__global__ void concat_g1_k() {
    int idx = blockIdx.x * 256 + threadIdx.x;
    if (idx >= NB*C1) return;
    int nb = idx >> 7, c = idx & 127;
    g_XS1[nb*LDA1 + c] = (c < UNITS) ? g_h0[nb*UNITS + c] : g_h1[nb*UNITS + c - UNITS];
}
__global__ void concat_c1_k() {
    int idx = blockIdx.x * 256 + threadIdx.x;
    if (idx >= NB*C1) return;
    int nb = idx >> 7, c = idx & 127;
    g_XS1[nb*LDA1 + c] = (c < UNITS) ? g_h0[nb*UNITS + c]
                                     : g_Gg[nb*(2*UNITS) + (c - UNITS)] * g_h1[nb*UNITS + c - UNITS];
}

// SpMM: XS[:, off_out] = S @ XS[:, off_in]  (optionally 2*S@x - x0, Chebyshev)
__global__ __launch_bounds__(256) void spmm_k(int sup, int lay, int C, int LDAv,
                                              int off_in, int off_out, int cheb) {
    const int*   rp = (sup == 1) ? g_ptr1 : g_ptr2;
    const int*   ci = (sup == 1) ? g_col1 : g_col2;
    const float* cv = (sup == 1) ? g_val1 : g_val2;
    float* XS = lay ? g_XS1 : g_XS0;
    int n  = blockIdx.x;
    int BC = BATCH * C;
    int j0 = blockIdx.y * 1024 + threadIdx.x;
    int inb[4]; float acc[4] = {0.f, 0.f, 0.f, 0.f};
#pragma unroll
    for (int i = 0; i < 4; i++) {
        int j = j0 + i*256;
        if (j < BC) { int b = j / C; int c = j - b*C; inb[i] = b*LDAv + off_in + c; }
        else inb[i] = -1;
    }
    int e0 = rp[n], e1 = rp[n+1];
    int rowstride = BATCH * LDAv;
    for (int e = e0; e < e1; e++) {
        int nbr = ci[e]; float v = cv[e];
        int base = nbr * rowstride;
#pragma unroll
        for (int i = 0; i < 4; i++)
            if (inb[i] >= 0) acc[i] += v * XS[base + inb[i]];
    }
    int obase = n * rowstride;
#pragma unroll
    for (int i = 0; i < 4; i++) {
        if (inb[i] >= 0) {
            float r = acc[i];
            if (cheb) r = 2.f*r - XS[obase + inb[i] - off_in];
            XS[obase + inb[i] - off_in + off_out] = r;
        }
    }
}

// ---------------- TF32 tensor-core GEMM ----------------
__device__ __forceinline__ unsigned f2tf(float f) {
    unsigned u; asm("cvt.rna.tf32.f32 %0, %1;" : "=r"(u) : "f"(f)); return u;
}
__device__ __forceinline__ float4 tf4(float4 v) {
    float4 r;
    r.x = __uint_as_float(f2tf(v.x)); r.y = __uint_as_float(f2tf(v.y));
    r.z = __uint_as_float(f2tf(v.z)); r.w = __uint_as_float(f2tf(v.w));
    return r;
}

// Out[65536, OUT] = act( X[65536, K(lda)] @ Wp[K, OUT] + bias )
// BM=128 BN=64 BK=16, 256 thr = 8 warps (4M x 2N), warp tile 32x32 via m16n8k8 TF32.
template<int ACT>
__global__ __launch_bounds__(256) void gemm_tc(int wsel, const float* __restrict__ bias,
                                               int outsel, int lay, int nkt, int lda, int OUT) {
    const float* __restrict__ Wp = (wsel==0) ? g_Wg0 : (wsel==1) ? g_Wc0
                                  : (wsel==2) ? g_Wg1 : g_Wc1;
    const float* __restrict__ X  = lay ? g_XS1 : g_XS0;
    float* __restrict__ Out = outsel ? g_Gc : g_Gg;
    __shared__ __align__(16) float As[2][128][20];   // m-major, stride 20 (conflict-free frags)
    __shared__ __align__(16) float Bs[2][16][72];    // k-major, stride 72 (conflict-free frags)
    const int tid = threadIdx.x, lane = tid & 31, warp = tid >> 5;
    const int m0 = blockIdx.x * 128, n0 = blockIdx.y * 64;
    const int wm = (warp >> 1) * 32, wn = (warp & 1) * 32;
    const int g = lane >> 2, t4 = lane & 3;

    float acc[2][4][4];
#pragma unroll
    for (int i = 0; i < 2; i++)
#pragma unroll
        for (int j = 0; j < 4; j++)
#pragma unroll
            for (int q = 0; q < 4; q++) acc[i][j][q] = 0.f;

    // A: 2 float4 per thread per tile (128x16); B: 1 float4 (16x64)
    int arow[2], akc[2];
#pragma unroll
    for (int it = 0; it < 2; it++) { int fid = tid + it*256; arow[it] = fid >> 2; akc[it] = (fid & 3) * 4; }
    const int brow = tid >> 4, bnc = (tid & 15) * 4;

    float4 ra[2], rb;
#pragma unroll
    for (int it = 0; it < 2; it++)
        ra[it] = *(const float4*)(X + (size_t)(m0 + arow[it]) * lda + akc[it]);
    rb = *(const float4*)(Wp + (size_t)brow * OUT + n0 + bnc);
#pragma unroll
    for (int it = 0; it < 2; it++) *(float4*)&As[0][arow[it]][akc[it]] = tf4(ra[it]);
    *(float4*)&Bs[0][brow][bnc] = tf4(rb);
    __syncthreads();

    for (int kt = 0; kt < nkt; kt++) {
        int cur = kt & 1;
        if (kt + 1 < nkt) {
            const float* Xp = X + (kt + 1) * 16;
#pragma unroll
            for (int it = 0; it < 2; it++)
                ra[it] = *(const float4*)(Xp + (size_t)(m0 + arow[it]) * lda + akc[it]);
            rb = *(const float4*)(Wp + (size_t)((kt + 1) * 16 + brow) * OUT + n0 + bnc);
        }
#pragma unroll
        for (int kk = 0; kk < 16; kk += 8) {
            unsigned af[2][4], bf[4][2];
#pragma unroll
            for (int i = 0; i < 2; i++) {
                af[i][0] = __float_as_uint(As[cur][wm + i*16 + g    ][kk + t4]);
                af[i][1] = __float_as_uint(As[cur][wm + i*16 + g + 8][kk + t4]);
                af[i][2] = __float_as_uint(As[cur][wm + i*16 + g    ][kk + t4 + 4]);
                af[i][3] = __float_as_uint(As[cur][wm + i*16 + g + 8][kk + t4 + 4]);
            }
#pragma unroll
            for (int j = 0; j < 4; j++) {
                bf[j][0] = __float_as_uint(Bs[cur][kk + t4    ][wn + j*8 + g]);
                bf[j][1] = __float_as_uint(Bs[cur][kk + t4 + 4][wn + j*8 + g]);
            }
#pragma unroll
            for (int i = 0; i < 2; i++)
#pragma unroll
                for (int j = 0; j < 4; j++)
                    asm volatile(
                        "mma.sync.aligned.m16n8k8.row.col.f32.tf32.tf32.f32 "
                        "{%0,%1,%2,%3}, {%4,%5,%6,%7}, {%8,%9}, {%0,%1,%2,%3};"
                        : "+f"(acc[i][j][0]), "+f"(acc[i][j][1]),
                          "+f"(acc[i][j][2]), "+f"(acc[i][j][3])
                        : "r"(af[i][0]), "r"(af[i][1]), "r"(af[i][2]), "r"(af[i][3]),
                          "r"(bf[j][0]), "r"(bf[j][1]));
        }
        if (kt + 1 < nkt) {
            int nxt = cur ^ 1;
#pragma unroll
            for (int it = 0; it < 2; it++) *(float4*)&As[nxt][arow[it]][akc[it]] = tf4(ra[it]);
            *(float4*)&Bs[nxt][brow][bnc] = tf4(rb);
        }
        __syncthreads();
    }

    // epilogue: bias + activation, write float2 pairs
#pragma unroll
    for (int j = 0; j < 4; j++) {
        int col = n0 + wn + j*8 + 2*t4;
        float b0 = bias[col], b1 = bias[col + 1];
#pragma unroll
        for (int i = 0; i < 2; i++) {
            int r0 = m0 + wm + i*16 + g;
            float v0 = acc[i][j][0] + b0, v1 = acc[i][j][1] + b1;
            float v2 = acc[i][j][2] + b0, v3 = acc[i][j][3] + b1;
            if (ACT == 1) {
                v0 = 1.f/(1.f+expf(-v0)); v1 = 1.f/(1.f+expf(-v1));
                v2 = 1.f/(1.f+expf(-v2)); v3 = 1.f/(1.f+expf(-v3));
            } else {
                v0 = tanhf(v0); v1 = tanhf(v1); v2 = tanhf(v2); v3 = tanhf(v3);
            }
            *(float2*)(Out + (size_t)r0 * OUT + col)       = make_float2(v0, v1);
            *(float2*)(Out + (size_t)(r0 + 8) * OUT + col) = make_float2(v2, v3);
        }
    }
}

__global__ void update_k(int hsel) {
    int idx = blockIdx.x * 256 + threadIdx.x;
    if (idx >= NB*UNITS) return;
    int nb = idx >> 6, k = idx & 63;
    float u = g_Gg[(nb << 7) + UNITS + k];
    float* h = hsel ? g_h1 : g_h0;
    h[idx] = u * h[idx] + (1.f - u) * g_Gc[idx];
}
__global__ void proj_k(const float* __restrict__ pw, const float* __restrict__ pb,
                       float* __restrict__ out, int t) {
    int idx = blockIdx.x * 256 + threadIdx.x;
    if (idx >= NB) return;
    int n = idx >> 7, b = idx & 127;
    float s = pb[0];
    const float* hh = &g_h1[idx * UNITS];
#pragma unroll
    for (int k = 0; k < UNITS; k++) s += hh[k] * pw[k];
    out[(b * T_OUTS + t) * N_NODES + n] = s;
    g_xin[idx] = s;
}

// ---------------- host orchestration ----------------
static void spmm4(int layer) {
    int C = layer ? C1 : C0;
    int L = layer ? LDA1 : LDA0;
    dim3 g(N_NODES, (BATCH*C + 1023) / 1024);
    spmm_k<<<g, 256>>>(1, layer, C, L, 0,   C,   0);
    spmm_k<<<g, 256>>>(1, layer, C, L, C,   2*C, 1);
    spmm_k<<<g, 256>>>(2, layer, C, L, 0,   3*C, 0);
    spmm_k<<<g, 256>>>(2, layer, C, L, 3*C, 4*C, 1);
}
static void launch_cell(int layer, const float* bg, const float* bc) {
    if (layer == 0) {
        concat_g0_k<<<(NB*C0 + 255)/256, 256>>>();
        spmm4(0);
        gemm_tc<1><<<dim3(512, 2), 256>>>(0, bg, 0, 0, K0P/16, LDA0, 2*UNITS);
        concat_c0_k<<<(NB*C0 + 255)/256, 256>>>();
        spmm4(0);
        gemm_tc<2><<<dim3(512, 1), 256>>>(1, bc, 1, 0, K0P/16, LDA0, UNITS);
        update_k<<<(NB*UNITS + 255)/256, 256>>>(0);
    } else {
        concat_g1_k<<<(NB*C1 + 255)/256, 256>>>();
        spmm4(1);
        gemm_tc<1><<<dim3(512, 2), 256>>>(2, bg, 0, 1, K1/16, LDA1, 2*UNITS);
        concat_c1_k<<<(NB*C1 + 255)/256, 256>>>();
        spmm4(1);
        gemm_tc<2><<<dim3(512, 1), 256>>>(3, bc, 1, 1, K1/16, LDA1, UNITS);
        update_k<<<(NB*UNITS + 255)/256, 256>>>(1);
    }
}

extern "C" void kernel_launch(void* const* d_in, const int* in_sizes, int n_in,
                              void* d_out, int out_size) {
    const float* hist = (const float*)d_in[0];
    const int*   ei   = (const int*)d_in[1];
    const float* ea   = (const float*)d_in[2];
    const float* W[16];
    for (int i = 0; i < 16; i++) W[i] = (const float*)d_in[3 + i];
    const float* pw = (const float*)d_in[19];
    const float* pb = (const float*)d_in[20];
    float* out = (float*)d_out;

    // --- supports setup ---
    zero_setup_k<<<(N_NODES*N_NODES)/256, 256>>>();
    zero_h_k<<<(NB*UNITS + 255)/256, 256>>>();
    scatter_k<<<E_EDGES/256, 256>>>(ei, ea);
    rowinv_k<<<N_NODES, 256>>>();
    colinv_k<<<2, 256>>>();
    count_k<<<(N_NODES*N_NODES)/256, 256>>>();
    scan_k<<<1, 32>>>();
    fill_k<<<(N_NODES*N_NODES)/256, 256>>>();

    // --- permute encoder weights ---
    permW_k<<<(K0*2*UNITS + 255)/256, 256>>>(W[0], 0, C0, 2*UNITS);
    permW_k<<<(K0*UNITS   + 255)/256, 256>>>(W[2], 1, C0, UNITS);
    permW_k<<<(K1*2*UNITS + 255)/256, 256>>>(W[4], 2, C1, 2*UNITS);
    permW_k<<<(K1*UNITS   + 255)/256, 256>>>(W[6], 3, C1, UNITS);

    // --- encoder ---
    for (int t = 0; t < T_INS; t++) {
        transpose_in_k<<<(NB + 255)/256, 256>>>(hist + (size_t)t * NB);
        launch_cell(0, W[1], W[3]);
        launch_cell(1, W[5], W[7]);
    }

    // --- permute decoder weights ---
    permW_k<<<(K0*2*UNITS + 255)/256, 256>>>(W[8],  0, C0, 2*UNITS);
    permW_k<<<(K0*UNITS   + 255)/256, 256>>>(W[10], 1, C0, UNITS);
    permW_k<<<(K1*2*UNITS + 255)/256, 256>>>(W[12], 2, C1, 2*UNITS);
    permW_k<<<(K1*UNITS   + 255)/256, 256>>>(W[14], 3, C1, UNITS);

    // --- decoder ---
    zero_xin_k<<<(NB + 255)/256, 256>>>();
    for (int t = 0; t < T_OUTS; t++) {
        launch_cell(0, W[9],  W[11]);
        launch_cell(1, W[13], W[15]);
        proj_k<<<(NB + 255)/256, 256>>>(pw, pb, out, t);
    }
}